// round 1
// baseline (speedup 1.0000x reference)
#include <cuda_runtime.h>
#include <cstdint>
#include <math.h>

// Problem constants (fixed by the benchmark's setup_inputs):
// B=64, S=512, Q=800, K=4, D=64  ->  GEMM: C[M=32768, N=64] = A[M,800] * Wq^T[800,64]
#define MDIM   32768
#define KDIM   800
#define NDIM   64
#define TM     128
#define TK     32
#define NITER  (KDIM / TK)   // 25
#define THREADS 128

// ---------------------------------------------------------------------------
// helpers
// ---------------------------------------------------------------------------
__device__ __forceinline__ uint32_t f2tf(float x) {
    uint32_t r;
    asm("cvt.rna.tf32.f32 %0, %1;" : "=r"(r) : "f"(x));
    return r;
}

__device__ __forceinline__ void cp16(uint32_t dst, const void* src) {
    asm volatile("cp.async.cg.shared.global [%0], [%1], 16;" :: "r"(dst), "l"(src));
}

__device__ __forceinline__ void mma_tf32(float* c,
                                         uint32_t a0, uint32_t a1, uint32_t a2, uint32_t a3,
                                         uint32_t b0, uint32_t b1) {
    asm volatile(
        "mma.sync.aligned.m16n8k8.row.col.f32.tf32.tf32.f32 "
        "{%0,%1,%2,%3}, {%4,%5,%6,%7}, {%8,%9}, {%0,%1,%2,%3};"
        : "+f"(c[0]), "+f"(c[1]), "+f"(c[2]), "+f"(c[3])
        : "r"(a0), "r"(a1), "r"(a2), "r"(a3), "r"(b0), "r"(b1));
}

// ---------------------------------------------------------------------------
// kernel
// ---------------------------------------------------------------------------
__global__ __launch_bounds__(THREADS)
void ordinal_embed_kernel(const float* __restrict__ q,
                          const int*   __restrict__ rdat,
                          const float* __restrict__ Wq,   // [64, 800] row-major
                          const float* __restrict__ bq,   // [64]
                          const float* __restrict__ Wr,   // [4]
                          const float* __restrict__ br,   // [1]
                          float*       __restrict__ out)  // [32768, 64]
{
    // XOR-swizzled tiles (stride 32 words; element (row,k) at row*32 + (k ^ ((row&7)*4)))
    // As: 2*128*32*4 = 32768 B, Bs: 2*64*32*4 = 16384 B  -> exactly 48 KB static.
    __shared__ float As[2][TM * TK];
    __shared__ float Bs[2][NDIM * TK];

    const int tid  = threadIdx.x;
    const int lane = tid & 31;
    const int w    = tid >> 5;         // warp id 0..3
    const int bm   = blockIdx.x;       // row-tile index

    float acc[2][8][4];
    #pragma unroll
    for (int mt = 0; mt < 2; ++mt)
        #pragma unroll
        for (int nt = 0; nt < 8; ++nt)
            #pragma unroll
            for (int i = 0; i < 4; ++i)
                acc[mt][nt][i] = 0.0f;

    const uint32_t asBase = (uint32_t)__cvta_generic_to_shared(&As[0][0]);
    const uint32_t bsBase = (uint32_t)__cvta_generic_to_shared(&Bs[0][0]);

    const float* aRowBase = q + (size_t)bm * TM * KDIM;

    // ---- stage(it) -> buffer it&1 ----
    // A: 128 rows x 32 floats = 1024 x 16B chunks, 8 per thread.
    // B: 64 rows  x 32 floats = 512  x 16B chunks, 4 per thread.
    #define STAGE(IT)                                                               \
    do {                                                                            \
        const int _buf = (IT) & 1;                                                  \
        const int _k0  = (IT) * TK;                                                 \
        _Pragma("unroll")                                                           \
        for (int i = 0; i < 8; ++i) {                                               \
            int ch = tid + THREADS * i;                                             \
            int m  = ch >> 3;                                                       \
            int kq = (ch & 7) * 4;                                                  \
            int widx = m * TK + (kq ^ ((m & 7) * 4));                               \
            cp16(asBase + (uint32_t)(_buf * (TM * TK) + widx) * 4u,                 \
                 aRowBase + (size_t)m * KDIM + _k0 + kq);                           \
        }                                                                           \
        _Pragma("unroll")                                                           \
        for (int i = 0; i < 4; ++i) {                                               \
            int ch = tid + THREADS * i;                                             \
            int n  = ch >> 3;                                                       \
            int kq = (ch & 7) * 4;                                                  \
            int widx = n * TK + (kq ^ ((n & 7) * 4));                               \
            cp16(bsBase + (uint32_t)(_buf * (NDIM * TK) + widx) * 4u,               \
                 Wq + (size_t)n * KDIM + _k0 + kq);                                 \
        }                                                                           \
        asm volatile("cp.async.commit_group;");                                     \
    } while (0)

    STAGE(0);

    for (int it = 0; it < NITER; ++it) {
        if (it + 1 < NITER) {
            STAGE(it + 1);
            asm volatile("cp.async.wait_group 1;");
        } else {
            asm volatile("cp.async.wait_group 0;");
        }
        __syncthreads();

        const float* A    = As[it & 1];
        const float* Bsh  = Bs[it & 1];

        #pragma unroll
        for (int k8 = 0; k8 < 4; ++k8) {
            const int kb = k8 * 8 + (lane & 3);

            // B fragments: 8 n-tiles x 2 regs (shared across warps via smem)
            uint32_t bf[8][2];
            #pragma unroll
            for (int nt = 0; nt < 8; ++nt) {
                int n = nt * 8 + (lane >> 2);
                int x = (n & 7) * 4;
                bf[nt][0] = f2tf(Bsh[n * TK + ( kb      ^ x)]);
                bf[nt][1] = f2tf(Bsh[n * TK + ((kb + 4) ^ x)]);
            }

            // A fragments: 2 m-tiles x 4 regs
            uint32_t af[2][4];
            #pragma unroll
            for (int mt = 0; mt < 2; ++mt) {
                int r0 = w * 32 + mt * 16 + (lane >> 2);
                int r1 = r0 + 8;                 // (r1 & 7) == (r0 & 7)
                int x  = (r0 & 7) * 4;
                af[mt][0] = f2tf(A[r0 * TK + ( kb      ^ x)]);
                af[mt][1] = f2tf(A[r1 * TK + ( kb      ^ x)]);
                af[mt][2] = f2tf(A[r0 * TK + ((kb + 4) ^ x)]);
                af[mt][3] = f2tf(A[r1 * TK + ((kb + 4) ^ x)]);
            }

            #pragma unroll
            for (int mt = 0; mt < 2; ++mt)
                #pragma unroll
                for (int nt = 0; nt < 8; ++nt)
                    mma_tf32(acc[mt][nt],
                             af[mt][0], af[mt][1], af[mt][2], af[mt][3],
                             bf[nt][0], bf[nt][1]);
        }
        __syncthreads();
    }

    // ---- epilogue: gate(r) * acc + bq ----
    const float wr0 = Wr[0], wr1 = Wr[1], wr2 = Wr[2], wr3 = Wr[3];
    const float brv = br[0];

    #pragma unroll
    for (int mt = 0; mt < 2; ++mt) {
        const int rbase = bm * TM + w * 32 + mt * 16 + (lane >> 2);
        #pragma unroll
        for (int h = 0; h < 2; ++h) {
            const int row = rbase + h * 8;
            const float rf = (float)rdat[row];
            // weights[k] = max(1 - |k - r|/3, 0)
            float s = brv;
            s += fmaxf(1.0f - fabsf(0.0f - rf) * (1.0f / 3.0f), 0.0f) * wr0;
            s += fmaxf(1.0f - fabsf(1.0f - rf) * (1.0f / 3.0f), 0.0f) * wr1;
            s += fmaxf(1.0f - fabsf(2.0f - rf) * (1.0f / 3.0f), 0.0f) * wr2;
            s += fmaxf(1.0f - fabsf(3.0f - rf) * (1.0f / 3.0f), 0.0f) * wr3;
            const float gate = 1.0f / (1.0f + expf(-s));

            #pragma unroll
            for (int nt = 0; nt < 8; ++nt) {
                const int col = nt * 8 + (lane & 3) * 2;
                float2 v;
                v.x = acc[mt][nt][h * 2 + 0] * gate + bq[col];
                v.y = acc[mt][nt][h * 2 + 1] * gate + bq[col + 1];
                *reinterpret_cast<float2*>(out + (size_t)row * NDIM + col) = v;
            }
        }
    }
}

// ---------------------------------------------------------------------------
// launch
// ---------------------------------------------------------------------------
extern "C" void kernel_launch(void* const* d_in, const int* in_sizes, int n_in,
                              void* d_out, int out_size) {
    const float* q    = (const float*)d_in[0];   // [64,512,800] f32
    const int*   rdat = (const int*)  d_in[1];   // [64,512]     i32
    const float* Wq   = (const float*)d_in[2];   // [64,800]     f32
    const float* bq   = (const float*)d_in[3];   // [64]         f32
    const float* Wr   = (const float*)d_in[4];   // [1,4]        f32
    const float* br   = (const float*)d_in[5];   // [1]          f32
    float* out = (float*)d_out;                  // [64,512,64]  f32

    ordinal_embed_kernel<<<MDIM / TM, THREADS>>>(q, rdat, Wq, bq, Wr, br, out);
}